// round 3
// baseline (speedup 1.0000x reference)
#include <cuda_runtime.h>
#include <math.h>

#define D_DIM 512
#define K_CODES 4096
#define N_TOK 32768
#define BM 128
#define BN 128
#define BK 16
#define TM 8
#define TN 8

// scratch (no allocations allowed)
__device__ int   g_indices[N_TOK];
__device__ int   g_counts[K_CODES];
__device__ float g_wnorm[K_CODES];
__device__ float g_xnorm[N_TOK];

// ---------------- kernel 0: ||x_m||^2, sequential scalar, mul+add (no FMA) ----------------
// Replicates XLA CPU's fused power+reduce loop: acc = fadd(acc, fmul(x,x)), i ascending.
__global__ void xnorm_kernel(const float* __restrict__ X) {
    int row = blockIdx.x * blockDim.x + threadIdx.x;
    if (row >= N_TOK) return;
    const float* x = X + (size_t)row * D_DIM;
    float s = 0.0f;
    for (int i = 0; i < D_DIM; i++) {
        float v = __ldg(&x[i]);
        s = __fadd_rn(s, __fmul_rn(v, v));
    }
    g_xnorm[row] = s;
}

// ---------------- kernel 1: ||w_k||^2, same sequential order ----------------
__global__ void wnorm_kernel(const float* __restrict__ W) {
    int row = blockIdx.x * blockDim.x + threadIdx.x;
    if (row >= K_CODES) return;
    const float* w = W + (size_t)row * D_DIM;
    float s = 0.0f;
    for (int i = 0; i < D_DIM; i++) {
        float v = __ldg(&w[i]);
        s = __fadd_rn(s, __fmul_rn(v, v));
    }
    g_wnorm[row] = s;
}

// ---------------- kernel 2: fused distance GEMM + argmin ----------------
// dot_k accumulated with k-ascending FFMA chain (matches Eigen fp32 gemm order).
// d = fl( fl(xnorm + wnorm_k) - 2*dot_k )   [2*dot exact], argmin w/ first-index tie-break.
__global__ __launch_bounds__(256) void dist_argmin_kernel(
    const float* __restrict__ X, const float* __restrict__ W)
{
    __shared__ union {
        struct { float Xs[BK][BM + 4]; float Ws[BK][BN + 4]; } t;
        struct { float rval[BM][16]; int ridx[BM][16]; } r;
    } sm;
    __shared__ float swnorm[BN];
    __shared__ float sxnorm[BM];

    const int tid = threadIdx.x;
    const int tx = tid & 15;        // 16 col groups
    const int ty = tid >> 4;        // 16 row groups
    const int m0 = blockIdx.x * BM;

    if (tid < BM) sxnorm[tid] = g_xnorm[m0 + tid];

    float best[TM];
    int   bidx[TM];
    #pragma unroll
    for (int i = 0; i < TM; i++) { best[i] = 3.4e38f; bidx[i] = 0x7fffffff; }

    for (int n0 = 0; n0 < K_CODES; n0 += BN) {
        if (tid < BN) swnorm[tid] = g_wnorm[n0 + tid];

        float acc[TM][TN];
        #pragma unroll
        for (int i = 0; i < TM; i++)
            #pragma unroll
            for (int j = 0; j < TN; j++) acc[i][j] = 0.f;

        for (int k0 = 0; k0 < D_DIM; k0 += BK) {
            // load X tile (BM x BK) transposed into smem, float4 global loads
            #pragma unroll
            for (int l = 0; l < 2; l++) {
                int idx4 = tid * 2 + l;          // 0..511
                int r = idx4 >> 2;               // 0..127
                int c4 = idx4 & 3;               // float4 slot within BK
                float4 v = *(const float4*)&X[(size_t)(m0 + r) * D_DIM + k0 + c4 * 4];
                sm.t.Xs[c4 * 4 + 0][r] = v.x;
                sm.t.Xs[c4 * 4 + 1][r] = v.y;
                sm.t.Xs[c4 * 4 + 2][r] = v.z;
                sm.t.Xs[c4 * 4 + 3][r] = v.w;
            }
            // load W tile (BN x BK) transposed
            #pragma unroll
            for (int l = 0; l < 2; l++) {
                int idx4 = tid * 2 + l;
                int r = idx4 >> 2;
                int c4 = idx4 & 3;
                float4 v = *(const float4*)&W[(size_t)(n0 + r) * D_DIM + k0 + c4 * 4];
                sm.t.Ws[c4 * 4 + 0][r] = v.x;
                sm.t.Ws[c4 * 4 + 1][r] = v.y;
                sm.t.Ws[c4 * 4 + 2][r] = v.z;
                sm.t.Ws[c4 * 4 + 3][r] = v.w;
            }
            __syncthreads();

            #pragma unroll
            for (int kk = 0; kk < BK; kk++) {
                float a[TM], b[TN];
                #pragma unroll
                for (int i = 0; i < TM; i++) a[i] = sm.t.Xs[kk][ty * TM + i];
                #pragma unroll
                for (int j = 0; j < TN; j++) b[j] = sm.t.Ws[kk][tx * TN + j];
                #pragma unroll
                for (int i = 0; i < TM; i++)
                    #pragma unroll
                    for (int j = 0; j < TN; j++)
                        acc[i][j] = __fmaf_rn(a[i], b[j], acc[i][j]);
            }
            __syncthreads();
        }

        // argmin update for this BN tile, replicating reference rounding:
        // d = fl( fl(xnorm + wnorm) - 2*dot ); first-index wins ties.
        #pragma unroll
        for (int i = 0; i < TM; i++) {
            float xn = sxnorm[ty * TM + i];
            #pragma unroll
            for (int j = 0; j < TN; j++) {
                float s = __fadd_rn(xn, swnorm[tx * TN + j]);
                float d = __fsub_rn(s, 2.0f * acc[i][j]);
                int n = n0 + tx * TN + j;
                if (d < best[i]) { best[i] = d; bidx[i] = n; }   // ascending n per thread
            }
        }
        __syncthreads();   // before smem reuse next iteration
    }

    // cross-thread (16 col-groups) argmin reduction per row, lowest index on ties
    #pragma unroll
    for (int i = 0; i < TM; i++) {
        sm.r.rval[ty * TM + i][tx] = best[i];
        sm.r.ridx[ty * TM + i][tx] = bidx[i];
    }
    __syncthreads();
    if (tid < BM) {
        float bv = sm.r.rval[tid][0];
        int   bi = sm.r.ridx[tid][0];
        #pragma unroll
        for (int t = 1; t < 16; t++) {
            float v = sm.r.rval[tid][t];
            int   ii = sm.r.ridx[tid][t];
            if (v < bv || (v == bv && ii < bi)) { bv = v; bi = ii; }
        }
        g_indices[m0 + tid] = bi;
    }
}

// ---------------- kernel 3: gather + quantized_st + loss + index-as-float ----------------
__global__ void epilogue_kernel(const float* __restrict__ X, const float* __restrict__ W,
                                float* __restrict__ out_q, float* __restrict__ out_loss,
                                float* __restrict__ out_idx, int write_loss, int write_idx)
{
    int t = blockIdx.x;
    int idx = g_indices[t];
    const float4* w = (const float4*)(W + (size_t)idx * D_DIM);
    const float4* x = (const float4*)(X + (size_t)t * D_DIM);
    float4* oq = (float4*)(out_q + (size_t)t * D_DIM);

    int c = threadIdx.x;   // 128 threads, 1 float4 each
    float4 qv = w[c];
    float4 xv = x[c];
    // quantized_st = x + (q - x)  (matches reference fp32 rounding exactly)
    float dx = __fsub_rn(qv.x, xv.x), dy = __fsub_rn(qv.y, xv.y);
    float dz = __fsub_rn(qv.z, xv.z), dw = __fsub_rn(qv.w, xv.w);
    float4 st;
    st.x = __fadd_rn(xv.x, dx); st.y = __fadd_rn(xv.y, dy);
    st.z = __fadd_rn(xv.z, dz); st.w = __fadd_rn(xv.w, dw);
    oq[c] = st;
    float s = dx * dx + dy * dy + dz * dz + dw * dw;

    // reduce over 128 threads
    #pragma unroll
    for (int o = 16; o > 0; o >>= 1) s += __shfl_down_sync(0xffffffffu, s, o);
    __shared__ float ws[4];
    if ((threadIdx.x & 31) == 0) ws[threadIdx.x >> 5] = s;
    __syncthreads();
    if (threadIdx.x == 0) {
        float tot = ws[0] + ws[1] + ws[2] + ws[3];
        if (write_loss) out_loss[t] = 1.25f * tot * (1.0f / D_DIM);
        if (write_idx)  out_idx[t] = (float)idx;
    }
}

// ---------------- kernel 4: zero counts ----------------
__global__ void zero_counts_kernel() {
    int i = blockIdx.x * blockDim.x + threadIdx.x;
    if (i < K_CODES) g_counts[i] = 0;
}

// ---------------- kernel 5: histogram ----------------
__global__ void hist_kernel(int M) {
    int i = blockIdx.x * blockDim.x + threadIdx.x;
    if (i < M) atomicAdd(&g_counts[g_indices[i]], 1);
}

// ---------------- kernel 6: perplexity ----------------
__global__ void perplexity_kernel(float* __restrict__ out_perp, int M) {
    __shared__ float ws[32];
    float inv = 1.0f / (float)M;
    float s = 0.f;
    for (int i = threadIdx.x; i < K_CODES; i += blockDim.x) {
        float p = (float)g_counts[i] * inv;
        s += p * logf(p + 1e-10f);
    }
    #pragma unroll
    for (int o = 16; o > 0; o >>= 1) s += __shfl_down_sync(0xffffffffu, s, o);
    if ((threadIdx.x & 31) == 0) ws[threadIdx.x >> 5] = s;
    __syncthreads();
    if (threadIdx.x == 0) {
        float tot = 0.f;
        int nw = blockDim.x >> 5;
        for (int w = 0; w < nw; w++) tot += ws[w];
        *out_perp = expf(-tot);
    }
}

extern "C" void kernel_launch(void* const* d_in, const int* in_sizes, int n_in,
                              void* d_out, int out_size)
{
    const float* X = (const float*)d_in[0];   // flat_input [M, 512]
    const float* W = (const float*)d_in[1];   // weight [4096, 512]
    const int M = in_sizes[0] / D_DIM;        // 32768

    float* out = (float*)d_out;
    float* out_q = out;
    size_t base = (size_t)M * D_DIM;
    int has_loss = out_size >= (int)(base + M);
    int has_perp = out_size >= (int)(base + M + 1);
    int has_idx  = out_size >= (int)(base + 2 * M + 1);

    float* out_loss = out + base;
    float* out_perp = out_loss + M;
    float* out_idx  = out_perp + 1;

    xnorm_kernel<<<(M + 255) / 256, 256>>>(X);
    wnorm_kernel<<<(K_CODES + 255) / 256, 256>>>(W);
    dist_argmin_kernel<<<M / BM, 256>>>(X, W);
    epilogue_kernel<<<M, 128>>>(X, W, out_q,
                                has_loss ? out_loss : out_q,
                                has_idx ? out_idx : out_q,
                                has_loss, has_idx);
    if (has_perp) {
        zero_counts_kernel<<<(K_CODES + 255) / 256, 256>>>();
        hist_kernel<<<(M + 255) / 256, 256>>>(M);
        perplexity_kernel<<<1, 1024>>>(out_perp, M);
    }
}

// round 5
// speedup vs baseline: 5.9741x; 5.9741x over previous
#include <cuda_runtime.h>
#include <cuda_bf16.h>
#include <math.h>
#include <stdint.h>

#define D_DIM 512
#define K_CODES 4096
#define N_TOK 32768
#define NT 32           // 32 code tiles of 128

// ---------------- device scratch (no allocations allowed) ----------------
__device__ int   g_indices[N_TOK];
__device__ int   g_counts[K_CODES];
__device__ float g_wnorm[K_CODES];
__device__ float g_xnorm[N_TOK];
__device__ __nv_bfloat16 g_Xb[(size_t)N_TOK * D_DIM];
__device__ __nv_bfloat16 g_Wb[(size_t)K_CODES * D_DIM];
__device__ float4 g_cand[(size_t)N_TOK * NT];   // per row per tile: {d1, idx1, d2, idx2}

// ---------------- PTX helpers (baseline ISA only: sm_80+) ----------------
__device__ __forceinline__ uint32_t smem_to_u32(const void* p) {
    uint32_t a;
    asm("{ .reg .u64 t; cvta.to.shared.u64 t, %1; cvt.u32.u64 %0, t; }" : "=r"(a) : "l"(p));
    return a;
}
#define LDSM_X4(r0, r1, r2, r3, addr) \
    asm volatile("ldmatrix.sync.aligned.m8n8.x4.shared.b16 {%0,%1,%2,%3}, [%4];" \
        : "=r"(r0), "=r"(r1), "=r"(r2), "=r"(r3) : "r"(addr))
#define MMA16816(d, a, b) \
    asm volatile("mma.sync.aligned.m16n8k16.row.col.f32.bf16.bf16.f32 " \
        "{%0,%1,%2,%3},{%4,%5,%6,%7},{%8,%9},{%0,%1,%2,%3};" \
        : "+f"((d)[0]), "+f"((d)[1]), "+f"((d)[2]), "+f"((d)[3]) \
        : "r"((a)[0]), "r"((a)[1]), "r"((a)[2]), "r"((a)[3]), "r"((b)[0]), "r"((b)[1]))
#define CP_ASYNC16(dst, src) \
    asm volatile("cp.async.cg.shared.global [%0], [%1], 16;" :: "r"(dst), "l"(src))
#define CP_COMMIT() asm volatile("cp.async.commit_group;" ::: "memory")
#define CP_WAIT0()  asm volatile("cp.async.wait_group 0;" ::: "memory")

// dynamic smem layout for stage1 (bytes)
#define S_MERGE 0                    // 4 KB  [128 rows][2 nhalf] float4
#define S_WN    4096                 // 16 KB wnorm
#define S_A     20480                // 128 KB A resident (128 x 512 bf16, swizzled)
#define S_B0    (S_A + 131072)       // 151552
#define S_B1    (S_B0 + 16384)       // 167936
#define S_TOT   (S_B1 + 16384)       // 184320

// ---------------- convert kernels ----------------
__global__ void cvtX_kernel(const float* __restrict__ X) {
    int i = blockIdx.x * blockDim.x + threadIdx.x;      // float4 index
    if (i >= N_TOK * D_DIM / 4) return;
    float4 v = ((const float4*)X)[i];
    __nv_bfloat162* d = (__nv_bfloat162*)g_Xb;
    d[2 * i]     = __floats2bfloat162_rn(v.x, v.y);
    d[2 * i + 1] = __floats2bfloat162_rn(v.z, v.w);
}
__global__ void cvtW_kernel(const float* __restrict__ W) {
    int i = blockIdx.x * blockDim.x + threadIdx.x;
    if (i >= K_CODES * D_DIM / 4) return;
    float4 v = ((const float4*)W)[i];
    __nv_bfloat162* d = (__nv_bfloat162*)g_Wb;
    d[2 * i]     = __floats2bfloat162_rn(v.x, v.y);
    d[2 * i + 1] = __floats2bfloat162_rn(v.z, v.w);
}

// ---------------- norm kernel (sequential fadd(fmul) per row — validated in R3) ----------------
__global__ void norm_kernel(const float* __restrict__ src, int which) {
    extern __shared__ float s[];               // [64][513]
    int r0 = blockIdx.x * 64;
    const float4* g = (const float4*)(src + (size_t)r0 * D_DIM);
    for (int u = threadIdx.x; u < 64 * 128; u += 256) {
        int row = u >> 7, c4 = u & 127;
        float4 v = g[(size_t)row * 128 + c4];
        float* p = s + row * 513 + c4 * 4;
        p[0] = v.x; p[1] = v.y; p[2] = v.z; p[3] = v.w;
    }
    __syncthreads();
    if (threadIdx.x < 64) {
        const float* p = s + threadIdx.x * 513;
        float acc = 0.f;
        #pragma unroll 8
        for (int i = 0; i < D_DIM; i++)
            acc = __fadd_rn(acc, __fmul_rn(p[i], p[i]));
        if (which) g_xnorm[r0 + threadIdx.x] = acc;
        else       g_wnorm[r0 + threadIdx.x] = acc;
    }
}

// ---------------- stage1: bf16 mma.sync GEMM + per-tile top-2 ----------------
__device__ __forceinline__ void issue_chunk(uint32_t sb, int tid, int g) {
    int t = g >> 3, kc = g & 7;
    const __nv_bfloat16* src = g_Wb + (size_t)(t * 128) * D_DIM + kc * 64;
    uint32_t buf = sb + ((g & 1) ? S_B1 : S_B0);
    #pragma unroll
    for (int i = 0; i < 8; i++) {
        int unit = i * 128 + tid;
        int nrow = unit >> 3, u = unit & 7;
        uint32_t dst = buf + nrow * 128 + ((u ^ (nrow & 7)) << 4);
        const void* gsrc = src + (size_t)nrow * D_DIM + u * 8;
        CP_ASYNC16(dst, gsrc);
    }
    CP_COMMIT();
}

__global__ void __launch_bounds__(128, 1) stage1_kernel() {
    extern __shared__ char smem[];
    const uint32_t sb = smem_to_u32(smem);
    const int tid = threadIdx.x;
    const int lane = tid & 31;
    const int w = tid >> 5;
    const int wm = w & 1, wn = w >> 1;     // warp tile: rows wm*64, cols wn*64
    const int m0 = blockIdx.x * 128;

    // wnorm -> smem
    {
        const float4* srcv = (const float4*)g_wnorm;
        float4* dstv = (float4*)(smem + S_WN);
        #pragma unroll
        for (int i = 0; i < 8; i++) dstv[i * 128 + tid] = srcv[i * 128 + tid];
    }
    // A resident: 128 rows x 512 bf16, 16B-unit swizzle u^(r&7)
    {
        const __nv_bfloat16* Xr = g_Xb + (size_t)m0 * D_DIM;
        #pragma unroll 8
        for (int it = 0; it < 64; it++) {
            int unit = it * 128 + tid;
            int r = unit >> 6, u = unit & 63;
            uint4 v = *(const uint4*)(Xr + (size_t)r * D_DIM + u * 8);
            *(uint4*)(smem + S_A + r * 1024 + ((u ^ (r & 7)) << 4)) = v;
        }
    }

    issue_chunk(sb, tid, 0);

    // per-lane ldmatrix addressing
    const int a_row = (lane & 7) + ((lane >> 3) & 1) * 8;   // matrix row within m16
    const int a_kh  = (lane >> 4) & 1;                      // k-half
    uint32_t a_base[4]; int a_x[4];
    #pragma unroll
    for (int mt = 0; mt < 4; mt++) {
        int r = wm * 64 + mt * 16 + a_row;
        a_base[mt] = sb + S_A + r * 1024;
        a_x[mt] = r & 7;
    }
    const int b_row_in = (lane & 7) + ((lane >> 4) & 1) * 8;
    const int b_kh     = (lane >> 3) & 1;
    uint32_t b_rowoff[4]; int b_x[4];
    #pragma unroll
    for (int p = 0; p < 4; p++) {
        int nr = wn * 64 + p * 16 + b_row_in;
        b_rowoff[p] = nr * 128;
        b_x[p] = nr & 7;
    }

    const int tg = lane & 3, g8 = lane >> 2;

    for (int t = 0; t < NT; t++) {
        float acc[4][8][4];
        #pragma unroll
        for (int mt = 0; mt < 4; mt++)
            #pragma unroll
            for (int nt = 0; nt < 8; nt++)
                #pragma unroll
                for (int e = 0; e < 4; e++) acc[mt][nt][e] = 0.f;

        for (int kc = 0; kc < 8; kc++) {
            int g = t * 8 + kc;
            CP_WAIT0();
            __syncthreads();
            if (g + 1 < NT * 8) issue_chunk(sb, tid, g + 1);
            uint32_t bbuf = sb + ((g & 1) ? S_B1 : S_B0);
            #pragma unroll
            for (int s = 0; s < 4; s++) {
                int gk = kc * 4 + s;
                uint32_t a[4][4];
                #pragma unroll
                for (int mt = 0; mt < 4; mt++) {
                    int u = gk * 2 + a_kh;
                    LDSM_X4(a[mt][0], a[mt][1], a[mt][2], a[mt][3],
                            a_base[mt] + ((u ^ a_x[mt]) << 4));
                }
                uint32_t b[8][2];
                #pragma unroll
                for (int p = 0; p < 4; p++) {
                    int u = s * 2 + b_kh;
                    uint32_t r0, r1, r2, r3;
                    LDSM_X4(r0, r1, r2, r3, bbuf + b_rowoff[p] + ((u ^ b_x[p]) << 4));
                    b[2 * p][0] = r0; b[2 * p][1] = r1;
                    b[2 * p + 1][0] = r2; b[2 * p + 1][1] = r3;
                }
                #pragma unroll
                for (int mt = 0; mt < 4; mt++)
                    #pragma unroll
                    for (int nt = 0; nt < 8; nt++)
                        MMA16816(acc[mt][nt], a[mt], b[nt]);
            }
        }

        // ---- per-tile top-2 epilogue ----
        #pragma unroll
        for (int mt = 0; mt < 4; mt++) {
            #pragma unroll
            for (int h = 0; h < 2; h++) {
                float v1 = 3.4e38f, v2 = 3.4e38f; int i1 = 0, i2 = 0;
                #pragma unroll
                for (int nt = 0; nt < 8; nt++) {
                    #pragma unroll
                    for (int e = 0; e < 2; e++) {
                        int col = wn * 64 + nt * 8 + tg * 2 + e;
                        int code = t * 128 + col;
                        float wnv = *(const float*)(smem + S_WN + code * 4);
                        float d = __fmaf_rn(-2.0f, acc[mt][nt][h * 2 + e], wnv);
                        if (d < v2) {
                            if (d < v1) { v2 = v1; i2 = i1; v1 = d; i1 = code; }
                            else        { v2 = d; i2 = code; }
                        }
                    }
                }
                #pragma unroll
                for (int off = 1; off <= 2; off <<= 1) {
                    float w1 = __shfl_xor_sync(0xffffffffu, v1, off);
                    int   j1 = __shfl_xor_sync(0xffffffffu, i1, off);
                    float w2 = __shfl_xor_sync(0xffffffffu, v2, off);
                    int   j2 = __shfl_xor_sync(0xffffffffu, i2, off);
                    if (w1 < v1) {
                        float nv2; int ni2;
                        if (v1 < w2) { nv2 = v1; ni2 = i1; } else { nv2 = w2; ni2 = j2; }
                        v1 = w1; i1 = j1; v2 = nv2; i2 = ni2;
                    } else if (w1 < v2) { v2 = w1; i2 = j1; }
                }
                if (tg == 0) {
                    int row = wm * 64 + mt * 16 + h * 8 + g8;
                    ((float4*)(smem + S_MERGE))[row * 2 + wn] =
                        make_float4(v1, __int_as_float(i1), v2, __int_as_float(i2));
                }
            }
        }
        __syncthreads();
        {
            float4 p = ((float4*)(smem + S_MERGE))[tid * 2 + 0];
            float4 q = ((float4*)(smem + S_MERGE))[tid * 2 + 1];
            float v1 = p.x; int i1 = __float_as_int(p.y);
            float v2 = p.z; int i2 = __float_as_int(p.w);
            if (q.x < v1) {
                float nv2 = (v1 < q.z) ? v1 : q.z;
                int   ni2 = (v1 < q.z) ? i1 : __float_as_int(q.w);
                v1 = q.x; i1 = __float_as_int(q.y); v2 = nv2; i2 = ni2;
            } else if (q.x < v2) { v2 = q.x; i2 = __float_as_int(q.y); }
            g_cand[(size_t)(m0 + tid) * NT + t] =
                make_float4(v1, __int_as_float(i1), v2, __int_as_float(i2));
        }
        __syncthreads();
    }
}

// ---------------- stage 2: top-8 select + exact fp32 rescore ----------------
__global__ void __launch_bounds__(256) stage2_kernel(const float* __restrict__ X,
                                                     const float* __restrict__ W) {
    const int warp = threadIdx.x >> 5, lane = threadIdx.x & 31;
    const int token = blockIdx.x * 8 + warp;
    const unsigned FULL = 0xffffffffu;

    float4 cv = g_cand[(size_t)token * NT + lane];   // one tile's top-2 per lane
    float cd0 = cv.x; int ci0 = __float_as_int(cv.y);
    float cd1 = cv.z; int ci1 = __float_as_int(cv.w);

    float xr[16];
    const float* x = X + (size_t)token * D_DIM;
    #pragma unroll
    for (int j = 0; j < 4; j++) {
        float4 v = *(const float4*)(x + j * 128 + lane * 4);
        xr[j * 4 + 0] = v.x; xr[j * 4 + 1] = v.y; xr[j * 4 + 2] = v.z; xr[j * 4 + 3] = v.w;
    }
    float xn = g_xnorm[token];
    float bd = 3.4e38f; int bi = 0x7fffffff;

    #pragma unroll
    for (int s = 0; s < 8; s++) {
        float md = fminf(cd0, cd1);
        float m = md;
        #pragma unroll
        for (int o = 16; o > 0; o >>= 1) m = fminf(m, __shfl_xor_sync(FULL, m, o));
        unsigned ball = __ballot_sync(FULL, md == m);
        int src = __ffs(ball) - 1;
        int pick = 0;
        if (lane == src) {
            if (cd0 <= cd1) { pick = ci0; cd0 = 3.4e38f; }
            else            { pick = ci1; cd1 = 3.4e38f; }
        }
        pick = __shfl_sync(FULL, pick, src);

        const float* wv = W + (size_t)pick * D_DIM;
        float acc = 0.f;
        #pragma unroll
        for (int j = 0; j < 4; j++) {
            float4 v = *(const float4*)(wv + j * 128 + lane * 4);
            acc = __fmaf_rn(xr[j * 4 + 0], v.x, acc);
            acc = __fmaf_rn(xr[j * 4 + 1], v.y, acc);
            acc = __fmaf_rn(xr[j * 4 + 2], v.z, acc);
            acc = __fmaf_rn(xr[j * 4 + 3], v.w, acc);
        }
        #pragma unroll
        for (int o = 16; o > 0; o >>= 1) acc += __shfl_xor_sync(FULL, acc, o);
        float dd = __fsub_rn(__fadd_rn(xn, g_wnorm[pick]), 2.0f * acc);
        if (dd < bd || (dd == bd && pick < bi)) { bd = dd; bi = pick; }
    }
    if (lane == 0) g_indices[token] = bi;
}

// ---------------- output epilogue / histogram / perplexity ----------------
__global__ void epilogue_kernel(const float* __restrict__ X, const float* __restrict__ W,
                                float* __restrict__ out_q, float* __restrict__ out_loss,
                                float* __restrict__ out_idx, int write_loss, int write_idx)
{
    int t = blockIdx.x;
    int idx = g_indices[t];
    const float4* w = (const float4*)(W + (size_t)idx * D_DIM);
    const float4* x = (const float4*)(X + (size_t)t * D_DIM);
    float4* oq = (float4*)(out_q + (size_t)t * D_DIM);

    int c = threadIdx.x;
    float4 qv = w[c];
    float4 xv = x[c];
    float dx = __fsub_rn(qv.x, xv.x), dy = __fsub_rn(qv.y, xv.y);
    float dz = __fsub_rn(qv.z, xv.z), dw = __fsub_rn(qv.w, xv.w);
    float4 st;
    st.x = __fadd_rn(xv.x, dx); st.y = __fadd_rn(xv.y, dy);
    st.z = __fadd_rn(xv.z, dz); st.w = __fadd_rn(xv.w, dw);
    oq[c] = st;
    float s = dx * dx + dy * dy + dz * dz + dw * dw;

    #pragma unroll
    for (int o = 16; o > 0; o >>= 1) s += __shfl_down_sync(0xffffffffu, s, o);
    __shared__ float ws[4];
    if ((threadIdx.x & 31) == 0) ws[threadIdx.x >> 5] = s;
    __syncthreads();
    if (threadIdx.x == 0) {
        float tot = ws[0] + ws[1] + ws[2] + ws[3];
        if (write_loss) out_loss[t] = 1.25f * tot * (1.0f / D_DIM);
        if (write_idx)  out_idx[t] = (float)idx;
    }
}
__global__ void zero_counts_kernel() {
    int i = blockIdx.x * blockDim.x + threadIdx.x;
    if (i < K_CODES) g_counts[i] = 0;
}
__global__ void hist_kernel(int M) {
    int i = blockIdx.x * blockDim.x + threadIdx.x;
    if (i < M) atomicAdd(&g_counts[g_indices[i]], 1);
}
__global__ void perplexity_kernel(float* __restrict__ out_perp, int M) {
    __shared__ float ws[32];
    float inv = 1.0f / (float)M;
    float s = 0.f;
    for (int i = threadIdx.x; i < K_CODES; i += blockDim.x) {
        float p = (float)g_counts[i] * inv;
        s += p * logf(p + 1e-10f);
    }
    #pragma unroll
    for (int o = 16; o > 0; o >>= 1) s += __shfl_down_sync(0xffffffffu, s, o);
    if ((threadIdx.x & 31) == 0) ws[threadIdx.x >> 5] = s;
    __syncthreads();
    if (threadIdx.x == 0) {
        float tot = 0.f;
        int nw = blockDim.x >> 5;
        for (int w = 0; w < nw; w++) tot += ws[w];
        *out_perp = expf(-tot);
    }
}

// ---------------- launch ----------------
extern "C" void kernel_launch(void* const* d_in, const int* in_sizes, int n_in,
                              void* d_out, int out_size)
{
    const float* X = (const float*)d_in[0];   // flat_input [32768, 512]
    const float* W = (const float*)d_in[1];   // weight [4096, 512]
    const int M = in_sizes[0] / D_DIM;

    float* out = (float*)d_out;
    float* out_q = out;
    size_t base = (size_t)M * D_DIM;
    int has_loss = out_size >= (int)(base + M);
    int has_perp = out_size >= (int)(base + M + 1);
    int has_idx  = out_size >= (int)(base + 2 * M + 1);
    float* out_loss = out + base;
    float* out_perp = out_loss + M;
    float* out_idx  = out_perp + 1;

    cudaFuncSetAttribute(stage1_kernel, cudaFuncAttributeMaxDynamicSharedMemorySize, S_TOT);
    cudaFuncSetAttribute(norm_kernel, cudaFuncAttributeMaxDynamicSharedMemorySize, 64 * 513 * 4);

    cvtX_kernel<<<(N_TOK * D_DIM / 4 + 255) / 256, 256>>>(X);
    cvtW_kernel<<<(K_CODES * D_DIM / 4 + 255) / 256, 256>>>(W);
    norm_kernel<<<M / 64, 256, 64 * 513 * 4>>>(X, 1);        // xnorm
    norm_kernel<<<K_CODES / 64, 256, 64 * 513 * 4>>>(W, 0);  // wnorm
    stage1_kernel<<<M / 128, 128, S_TOT>>>();
    stage2_kernel<<<M / 8, 256>>>(X, W);
    epilogue_kernel<<<M, 128>>>(X, W, out_q,
                                has_loss ? out_loss : out_q,
                                has_idx ? out_idx : out_q,
                                has_loss, has_idx);
    if (has_perp) {
        zero_counts_kernel<<<(K_CODES + 255) / 256, 256>>>();
        hist_kernel<<<(M + 255) / 256, 256>>>(M);
        perplexity_kernel<<<1, 1024>>>(out_perp, M);
    }
}